// round 11
// baseline (speedup 1.0000x reference)
#include <cuda_runtime.h>
#include <cstdint>

// out[n,c,oh,ow] = x[n,c,2*oh,2*ow]
//   x:   (8,128,512,512) fp32, contiguous NCHW  -> 268,435,456 elems
//   out: (8,128,256,256) fp32                    ->  67,108,864 elems
//
// One WARP per TWO adjacent output rows (rows 2g, 2g+1 -> input rows 4g,
// 4g+2). Lane k loads contiguous float4s at lane + 32*j — fully coalesced
// (4 L1 wavefronts per LDG). The even elements (.x,.z) of lane k's float4
// are exactly output floats 2k,2k+1 = output float2 index k: deinterleave
// is free, no shuffles. 8 independent loads front-batched (MLP_p1=8) to
// keep the DRAM pipe full, then 8 coalesced STG.64.

static constexpr int OUT_ROWS   = 8 * 128 * 256;  // 262,144 output rows
static constexpr int IN_ROW_F4  = 128;            // float4 per input row
static constexpr int OUT_ROW_F2 = 128;            // float2 per output row
static constexpr int WARPS_PER_BLOCK = 8;         // 256 threads

__global__ __launch_bounds__(256) void strided_slice_kernel(
    const float4* __restrict__ in, float2* __restrict__ out)
{
    int gwarp = (blockIdx.x * blockDim.x + threadIdx.x) >> 5;
    int lane  = threadIdx.x & 31;

    // output rows 2*gwarp and 2*gwarp+1 -> input rows 4*gwarp, 4*gwarp+2
    const float4* irow0 = in  + (long)gwarp * (4 * IN_ROW_F4);
    const float4* irow1 = irow0 + 2 * IN_ROW_F4;
    float2*       orow0 = out + (long)gwarp * (2 * OUT_ROW_F2);
    float2*       orow1 = orow0 + OUT_ROW_F2;

    // 8 independent, warp-contiguous 128-bit loads
    float4 a0 = __ldcs(irow0 + lane);
    float4 a1 = __ldcs(irow0 + lane + 32);
    float4 a2 = __ldcs(irow0 + lane + 64);
    float4 a3 = __ldcs(irow0 + lane + 96);
    float4 b0 = __ldcs(irow1 + lane);
    float4 b1 = __ldcs(irow1 + lane + 32);
    float4 b2 = __ldcs(irow1 + lane + 64);
    float4 b3 = __ldcs(irow1 + lane + 96);

    __stcs(orow0 + lane,      make_float2(a0.x, a0.z));
    __stcs(orow0 + lane + 32, make_float2(a1.x, a1.z));
    __stcs(orow0 + lane + 64, make_float2(a2.x, a2.z));
    __stcs(orow0 + lane + 96, make_float2(a3.x, a3.z));
    __stcs(orow1 + lane,      make_float2(b0.x, b0.z));
    __stcs(orow1 + lane + 32, make_float2(b1.x, b1.z));
    __stcs(orow1 + lane + 64, make_float2(b2.x, b2.z));
    __stcs(orow1 + lane + 96, make_float2(b3.x, b3.z));
}

extern "C" void kernel_launch(void* const* d_in, const int* in_sizes, int n_in,
                              void* d_out, int out_size)
{
    const float4* in  = (const float4*)d_in[0];
    float2*       out = (float2*)d_out;

    int warps  = OUT_ROWS / 2;                 // 131,072 warps
    int blocks = warps / WARPS_PER_BLOCK;      // 16,384 blocks x 256 threads
    strided_slice_kernel<<<blocks, 256>>>(in, out);
}

// round 12
// speedup vs baseline: 1.0197x; 1.0197x over previous
#include <cuda_runtime.h>
#include <cstdint>

// out[n,c,oh,ow] = x[n,c,2*oh,2*ow]
//   x:   (8,128,512,512) fp32, contiguous NCHW  -> 268,435,456 elems
//   out: (8,128,256,256) fp32                    ->  67,108,864 elems
//
// One WARP per output row (R8 winner structure). Lane k loads contiguous
// float4 irow[k + 32*j] (j=0..3) — fully coalesced, dense 512B per warp
// per LDG. The even elements (.x,.z) of lane k's float4 are exactly output
// floats 2k,2k+1 = output float2 index k: deinterleave is free, no
// shuffles. 4 independent loads front-batched, 4 coalesced STG.64.
// Measured at the HBM roofline: 6.88 TB/s (86.8% DRAM duty); the residual
// is read/write turnaround on a 2:1 mixed stream, not kernel-addressable.

static constexpr int OUT_ROWS   = 8 * 128 * 256;  // 262,144 output rows
static constexpr int IN_ROW_F4  = 128;            // float4 per input row
static constexpr int OUT_ROW_F2 = 128;            // float2 per output row
static constexpr int THREADS    = 512;            // 16 warps per block
static constexpr int WARPS_PER_BLOCK = THREADS / 32;

__global__ __launch_bounds__(THREADS) void strided_slice_kernel(
    const float4* __restrict__ in, float2* __restrict__ out)
{
    int gwarp = (blockIdx.x * blockDim.x + threadIdx.x) >> 5;  // output row r
    int lane  = threadIdx.x & 31;

    // input row 2*r starts at float4 index (2*r)*128
    const float4* irow = in  + (long)gwarp * (2 * IN_ROW_F4);
    float2*       orow = out + (long)gwarp * OUT_ROW_F2;

    // 4 independent, warp-contiguous 128-bit streaming loads
    float4 a = __ldcs(irow + lane);
    float4 b = __ldcs(irow + lane + 32);
    float4 c = __ldcs(irow + lane + 64);
    float4 d = __ldcs(irow + lane + 96);

    // even elements -> output float2 at the same lane index: free deinterleave
    __stcs(orow + lane,      make_float2(a.x, a.z));
    __stcs(orow + lane + 32, make_float2(b.x, b.z));
    __stcs(orow + lane + 64, make_float2(c.x, c.z));
    __stcs(orow + lane + 96, make_float2(d.x, d.z));
}

extern "C" void kernel_launch(void* const* d_in, const int* in_sizes, int n_in,
                              void* d_out, int out_size)
{
    const float4* in  = (const float4*)d_in[0];
    float2*       out = (float2*)d_out;

    int blocks = OUT_ROWS / WARPS_PER_BLOCK;  // 16,384 blocks x 512 threads
    strided_slice_kernel<<<blocks, THREADS>>>(in, out);
}